// round 2
// baseline (speedup 1.0000x reference)
#include <cuda_runtime.h>

// Problem constants
#define BB 2
#define NN 200000
#define CC 16
#define DD 256
#define HH 256
#define WW 32
#define VV (DD * HH * WW)          // 2097152 = 2^21
#define LOGV 21

// Scratch: zero-initialized at module load. Invariant maintained by
// finalize_kernel: scratch is all-zero at entry of every kernel_launch.
__device__ float4 g_sums[(size_t)BB * VV * 4];   // [B,V,16] fp32, as 4x float4 per voxel
__device__ float  g_cnt[(size_t)BB * VV];        // [B,V]

__device__ __forceinline__ int voxel_idx(float p, float lo, float range, float dim, int dmax) {
    // Mirror reference exactly: (p - lo) / (hi - lo) * D, truncate, clamp
    float t = __fmul_rn(__fdiv_rn(__fsub_rn(p, lo), range), dim);
    int i = (int)t;                // trunc toward zero, matches astype(int32)
    i = i < 0 ? 0 : i;
    i = i > dmax ? dmax : i;
    return i;
}

__global__ void __launch_bounds__(256) scatter_kernel(const float* __restrict__ pts,
                                                      const float* __restrict__ fts) {
    int t = blockIdx.x * blockDim.x + threadIdx.x;
    if (t >= BB * NN) return;

    float x = pts[3 * t + 0];
    float y = pts[3 * t + 1];
    float z = pts[3 * t + 2];

    int vx = voxel_idx(x, -48.0f, 96.0f, 256.0f, DD - 1);
    int vy = voxel_idx(y, -48.0f, 96.0f, 256.0f, HH - 1);
    int vz = voxel_idx(z,  -4.0f,  5.5f,  32.0f, WW - 1);

    int flat = (vx * HH + vy) * WW + vz;
    int b = (t >= NN) ? 1 : 0;
    size_t g = ((size_t)b << LOGV) + (size_t)flat;

    atomicAdd(&g_cnt[g], 1.0f);

    const float4* f = reinterpret_cast<const float4*>(fts + (size_t)t * CC);
    float4* s = &g_sums[g * 4];
#pragma unroll
    for (int i = 0; i < 4; i++) {
        float4 v = f[i];
        asm volatile("red.global.add.v4.f32 [%0], {%1,%2,%3,%4};"
                     :: "l"(s + i), "f"(v.x), "f"(v.y), "f"(v.z), "f"(v.w)
                     : "memory");
    }
}

// Each thread finalizes 4 consecutive voxels -> all loads/stores are 128-bit.
__global__ void __launch_bounds__(256) finalize_kernel(float* __restrict__ out) {
    int t = blockIdx.x * blockDim.x + threadIdx.x;   // 0 .. B*V/4-1
    int g0 = t << 2;                                  // base voxel (global)
    int b = g0 >> LOGV;
    int v = g0 & (VV - 1);

    float4 c4 = *reinterpret_cast<const float4*>(&g_cnt[g0]);
    float cc[4] = {c4.x, c4.y, c4.z, c4.w};
    float r[4];
    bool ne[4];
#pragma unroll
    for (int i = 0; i < 4; i++) {
        ne[i] = cc[i] > 0.0f;
        r[i] = ne[i] ? __frcp_rn(cc[i]) : 0.0f;
    }

    float* o = out + (size_t)b * CC * VV + v;
    float4* sbase = &g_sums[(size_t)g0 * 4];          // voxel g occupies sbase[ (g-g0)*4 .. +4 )
    const float4 z4 = make_float4(0.f, 0.f, 0.f, 0.f);

#pragma unroll
    for (int grp = 0; grp < 4; grp++) {               // channel group 4*grp .. 4*grp+3
        float4 sv[4];
#pragma unroll
        for (int vi = 0; vi < 4; vi++) {
            if (ne[vi]) {
                float4 s = sbase[vi * 4 + grp];
                s.x *= r[vi]; s.y *= r[vi]; s.z *= r[vi]; s.w *= r[vi];
                sv[vi] = s;
                sbase[vi * 4 + grp] = z4;             // re-zero scratch (dirty only)
            } else {
                sv[vi] = z4;
            }
        }
        // transpose: 4 voxels x 4 channels -> 4 channel-major float4 stores
        {
            float4 ov;
            ov.x = sv[0].x; ov.y = sv[1].x; ov.z = sv[2].x; ov.w = sv[3].x;
            *reinterpret_cast<float4*>(o + (size_t)(4 * grp + 0) * VV) = ov;
            ov.x = sv[0].y; ov.y = sv[1].y; ov.z = sv[2].y; ov.w = sv[3].y;
            *reinterpret_cast<float4*>(o + (size_t)(4 * grp + 1) * VV) = ov;
            ov.x = sv[0].z; ov.y = sv[1].z; ov.z = sv[2].z; ov.w = sv[3].z;
            *reinterpret_cast<float4*>(o + (size_t)(4 * grp + 2) * VV) = ov;
            ov.x = sv[0].w; ov.y = sv[1].w; ov.z = sv[2].w; ov.w = sv[3].w;
            *reinterpret_cast<float4*>(o + (size_t)(4 * grp + 3) * VV) = ov;
        }
    }

    if (ne[0] | ne[1] | ne[2] | ne[3]) {
        *reinterpret_cast<float4*>(&g_cnt[g0]) = z4;  // re-zero counts (dirty lines only)
    }
}

extern "C" void kernel_launch(void* const* d_in, const int* in_sizes, int n_in,
                              void* d_out, int out_size) {
    const float* pts = (const float*)d_in[0];   // [B,N,3] f32
    const float* fts = (const float*)d_in[1];   // [B,N,16] f32
    float* out = (float*)d_out;                 // [B,16,D,H,W] f32

    const int npts = BB * NN;
    scatter_kernel<<<(npts + 255) / 256, 256>>>(pts, fts);

    const int nthreads = (BB * VV) / 4;         // 4 voxels per thread
    finalize_kernel<<<nthreads / 256, 256>>>(out);
}